// round 2
// baseline (speedup 1.0000x reference)
#include <cuda_runtime.h>
#include <math.h>

#define NV 6
#define C  16
#define H  480
#define W  640
#define D  96
#define P  (D*D*D)           // 884736
#define NPIX (NV*H*W)        // 1843200

// Scratch: transposed features (v, h, w, c) channel-last, 16B aligned.
__device__ __align__(16) float g_ft[(size_t)NPIX * C];
// Fused projection matrices: A[v] = K[v] @ inv(c2w[v]) (3x4 row-major)
__device__ float g_proj[NV][12];

// ---------------------------------------------------------------------------
// Kernel 1: compute per-view 3x4 projection matrices (6 threads total)
// ---------------------------------------------------------------------------
__global__ void prep_kernel(const float* __restrict__ intrs,
                            const float* __restrict__ c2ws) {
    int v = threadIdx.x;
    if (v >= NV) return;
    const float* M = c2ws + v * 16;   // row-major 4x4, last row [0,0,0,1]
    float R00=M[0],  R01=M[1],  R02=M[2],  t0=M[3];
    float R10=M[4],  R11=M[5],  R12=M[6],  t1=M[7];
    float R20=M[8],  R21=M[9],  R22=M[10], t2=M[11];
    // rigid inverse: w2c = [R^T | -R^T t]
    float w2c[3][4];
    w2c[0][0]=R00; w2c[0][1]=R10; w2c[0][2]=R20;
    w2c[1][0]=R01; w2c[1][1]=R11; w2c[1][2]=R21;
    w2c[2][0]=R02; w2c[2][1]=R12; w2c[2][2]=R22;
    w2c[0][3] = -(w2c[0][0]*t0 + w2c[0][1]*t1 + w2c[0][2]*t2);
    w2c[1][3] = -(w2c[1][0]*t0 + w2c[1][1]*t1 + w2c[1][2]*t2);
    w2c[2][3] = -(w2c[2][0]*t0 + w2c[2][1]*t1 + w2c[2][2]*t2);
    const float* K = intrs + v * 12;  // 3x4, K[:,3]=0
    for (int i = 0; i < 3; i++)
        for (int j = 0; j < 4; j++)
            g_proj[v][i*4 + j] = K[i*4+0]*w2c[0][j]
                               + K[i*4+1]*w2c[1][j]
                               + K[i*4+2]*w2c[2][j];
}

// ---------------------------------------------------------------------------
// Kernel 2: transpose features (v, c, h, w) -> (v, h, w, c)
// Reads coalesced per channel plane; writes 64B contiguous per pixel.
// ---------------------------------------------------------------------------
__global__ void __launch_bounds__(256) transpose_kernel(const float* __restrict__ feat) {
    int idx = blockIdx.x * 256 + threadIdx.x;   // over NV*H*W (exact multiple)
    int v   = idx / (H * W);
    int pix = idx - v * (H * W);
    const float* src = feat + (size_t)v * C * H * W + pix;
    float4* dst = reinterpret_cast<float4*>(&g_ft[(size_t)idx * C]);
#pragma unroll
    for (int q = 0; q < 4; q++) {
        float4 r;
        r.x = __ldg(src + (size_t)(q*4 + 0) * H * W);
        r.y = __ldg(src + (size_t)(q*4 + 1) * H * W);
        r.z = __ldg(src + (size_t)(q*4 + 2) * H * W);
        r.w = __ldg(src + (size_t)(q*4 + 3) * H * W);
        dst[q] = r;
    }
}

// ---------------------------------------------------------------------------
// Kernel 3: main cost-volume kernel. One thread per voxel.
// ---------------------------------------------------------------------------
__global__ void __launch_bounds__(256) vol_kernel(float* __restrict__ out) {
    __shared__ float s_proj[NV * 12];
    if (threadIdx.x < NV * 12)
        s_proj[threadIdx.x] = ((const float*)g_proj)[threadIdx.x];
    __syncthreads();

    int p = blockIdx.x * 256 + threadIdx.x;     // P is exact multiple of 256
    int k = p % D;
    int j = (p / D) % D;
    int i = p / (D * D);

    const float step = 2.0f / 95.0f;
    float wx = -1.0f + step * (float)i;
    float wy = -1.0f + step * (float)j;
    float wz = -1.0f + step * (float)k;

    float sum[C];
    float sq[C];
#pragma unroll
    for (int c = 0; c < C; c++) { sum[c] = 0.0f; sq[c] = 0.0f; }
    float msum = 0.0f;

#pragma unroll
    for (int v = 0; v < NV; v++) {
        const float* A = &s_proj[v * 12];
        float px = A[0]*wx + A[1]*wy + A[2]*wz  + A[3];
        float py = A[4]*wx + A[5]*wy + A[6]*wz  + A[7];
        float pz = A[8]*wx + A[9]*wy + A[10]*wz + A[11];
        if (pz > 0.0f) {
            float inv = 1.0f / (pz + 1e-8f);
            float ix = px * inv;
            float iy = py * inv;
            if (ix >= 0.0f && ix <= (float)(W - 1) &&
                iy >= 0.0f && iy <= (float)(H - 1)) {
                msum += 1.0f;
                float fx0 = floorf(ix), fy0 = floorf(iy);
                int x0 = (int)fx0, y0 = (int)fy0;
                float wx1 = ix - fx0, wy1 = iy - fy0;
                float wx0 = 1.0f - wx1, wy0 = 1.0f - wy1;
                int x1 = min(x0 + 1, W - 1);
                int y1 = min(y0 + 1, H - 1);
                float w00 = wx0 * wy0, w01 = wx1 * wy0;
                float w10 = wx0 * wy1, w11 = wx1 * wy1;
                size_t base = (size_t)v * H * W;
                const float4* b00 = reinterpret_cast<const float4*>(&g_ft[(base + (size_t)y0*W + x0) * C]);
                const float4* b01 = reinterpret_cast<const float4*>(&g_ft[(base + (size_t)y0*W + x1) * C]);
                const float4* b10 = reinterpret_cast<const float4*>(&g_ft[(base + (size_t)y1*W + x0) * C]);
                const float4* b11 = reinterpret_cast<const float4*>(&g_ft[(base + (size_t)y1*W + x1) * C]);
#pragma unroll
                for (int q = 0; q < 4; q++) {
                    float4 p00 = __ldg(b00 + q);
                    float4 p01 = __ldg(b01 + q);
                    float4 p10 = __ldg(b10 + q);
                    float4 p11 = __ldg(b11 + q);
                    float v0 = w00*p00.x + w01*p01.x + w10*p10.x + w11*p11.x;
                    float v1 = w00*p00.y + w01*p01.y + w10*p10.y + w11*p11.y;
                    float v2 = w00*p00.z + w01*p01.z + w10*p10.z + w11*p11.z;
                    float v3 = w00*p00.w + w01*p01.w + w10*p10.w + w11*p11.w;
                    int c = q * 4;
                    sum[c+0] += v0; sq[c+0] += v0*v0;
                    sum[c+1] += v1; sq[c+1] += v1*v1;
                    sum[c+2] += v2; sq[c+2] += v2*v2;
                    sum[c+3] += v3; sq[c+3] += v3*v3;
                }
            }
        }
    }

    float denom = (msum <= 0.0f) ? 1e-8f : msum;
    float rd = 1.0f / denom;
#pragma unroll
    for (int c = 0; c < C; c++) {
        float mean = sum[c] * rd;
        float var  = sq[c] * rd - mean * mean;
        out[(size_t)c * P + p]       = mean;
        out[(size_t)(C + c) * P + p] = var;
    }
    out[(size_t)(2 * C) * P + p] = (msum > 1.0f) ? 1.0f : 0.0f;
}

// ---------------------------------------------------------------------------
extern "C" void kernel_launch(void* const* d_in, const int* in_sizes, int n_in,
                              void* d_out, int out_size) {
    const float* features = (const float*)d_in[0];  // (6,16,480,640)
    const float* intrs    = (const float*)d_in[1];  // (6,3,4)
    const float* c2ws     = (const float*)d_in[2];  // (6,4,4)
    float* out = (float*)d_out;                     // 33 * 96^3 floats

    prep_kernel<<<1, 32>>>(intrs, c2ws);
    transpose_kernel<<<NPIX / 256, 256>>>(features);
    vol_kernel<<<P / 256, 256>>>(out);
    (void)in_sizes; (void)n_in; (void)out_size;
}

// round 3
// speedup vs baseline: 1.0018x; 1.0018x over previous
#include <cuda_runtime.h>
#include <math.h>

#define NV 6
#define C  16
#define H  480
#define W  640
#define D  96
#define P  (D*D*D)           // 884736
#define NPIX (NV*H*W)        // 1843200

// Scratch: transposed features (v, h, w, c) channel-last, 16B aligned.
__device__ __align__(16) float g_ft[(size_t)NPIX * C];
// Fused projection matrices: A[v] = K[v] @ inv(c2w[v]) (3x4 row-major)
__device__ float g_proj[NV][12];

// ---------------------------------------------------------------------------
// Kernel 1: compute per-view 3x4 projection matrices (6 threads total)
// ---------------------------------------------------------------------------
__global__ void prep_kernel(const float* __restrict__ intrs,
                            const float* __restrict__ c2ws) {
    int v = threadIdx.x;
    if (v >= NV) return;
    const float* M = c2ws + v * 16;   // row-major 4x4, last row [0,0,0,1]
    float R00=M[0],  R01=M[1],  R02=M[2],  t0=M[3];
    float R10=M[4],  R11=M[5],  R12=M[6],  t1=M[7];
    float R20=M[8],  R21=M[9],  R22=M[10], t2=M[11];
    // rigid inverse: w2c = [R^T | -R^T t]
    float w2c[3][4];
    w2c[0][0]=R00; w2c[0][1]=R10; w2c[0][2]=R20;
    w2c[1][0]=R01; w2c[1][1]=R11; w2c[1][2]=R21;
    w2c[2][0]=R02; w2c[2][1]=R12; w2c[2][2]=R22;
    w2c[0][3] = -(w2c[0][0]*t0 + w2c[0][1]*t1 + w2c[0][2]*t2);
    w2c[1][3] = -(w2c[1][0]*t0 + w2c[1][1]*t1 + w2c[1][2]*t2);
    w2c[2][3] = -(w2c[2][0]*t0 + w2c[2][1]*t1 + w2c[2][2]*t2);
    const float* K = intrs + v * 12;  // 3x4, K[:,3]=0
    for (int i = 0; i < 3; i++)
        for (int j = 0; j < 4; j++)
            g_proj[v][i*4 + j] = K[i*4+0]*w2c[0][j]
                               + K[i*4+1]*w2c[1][j]
                               + K[i*4+2]*w2c[2][j];
}

// ---------------------------------------------------------------------------
// Kernel 2: transpose features (v, c, h, w) -> (v, h, w, c)
// Reads coalesced per channel plane; writes 64B contiguous per pixel.
// ---------------------------------------------------------------------------
__global__ void __launch_bounds__(256) transpose_kernel(const float* __restrict__ feat) {
    int idx = blockIdx.x * 256 + threadIdx.x;   // over NV*H*W (exact multiple)
    int v   = idx / (H * W);
    int pix = idx - v * (H * W);
    const float* src = feat + (size_t)v * C * H * W + pix;
    float4* dst = reinterpret_cast<float4*>(&g_ft[(size_t)idx * C]);
#pragma unroll
    for (int q = 0; q < 4; q++) {
        float4 r;
        r.x = __ldg(src + (size_t)(q*4 + 0) * H * W);
        r.y = __ldg(src + (size_t)(q*4 + 1) * H * W);
        r.z = __ldg(src + (size_t)(q*4 + 2) * H * W);
        r.w = __ldg(src + (size_t)(q*4 + 3) * H * W);
        dst[q] = r;
    }
}

// ---------------------------------------------------------------------------
// Kernel 3: main cost-volume kernel. One thread per voxel.
// ---------------------------------------------------------------------------
__global__ void __launch_bounds__(256) vol_kernel(float* __restrict__ out) {
    __shared__ float s_proj[NV * 12];
    if (threadIdx.x < NV * 12)
        s_proj[threadIdx.x] = ((const float*)g_proj)[threadIdx.x];
    __syncthreads();

    int p = blockIdx.x * 256 + threadIdx.x;     // P is exact multiple of 256
    int k = p % D;
    int j = (p / D) % D;
    int i = p / (D * D);

    const float step = 2.0f / 95.0f;
    float wx = -1.0f + step * (float)i;
    float wy = -1.0f + step * (float)j;
    float wz = -1.0f + step * (float)k;

    float sum[C];
    float sq[C];
#pragma unroll
    for (int c = 0; c < C; c++) { sum[c] = 0.0f; sq[c] = 0.0f; }
    float msum = 0.0f;

#pragma unroll
    for (int v = 0; v < NV; v++) {
        const float* A = &s_proj[v * 12];
        float px = A[0]*wx + A[1]*wy + A[2]*wz  + A[3];
        float py = A[4]*wx + A[5]*wy + A[6]*wz  + A[7];
        float pz = A[8]*wx + A[9]*wy + A[10]*wz + A[11];
        if (pz > 0.0f) {
            float inv = 1.0f / (pz + 1e-8f);
            float ix = px * inv;
            float iy = py * inv;
            if (ix >= 0.0f && ix <= (float)(W - 1) &&
                iy >= 0.0f && iy <= (float)(H - 1)) {
                msum += 1.0f;
                float fx0 = floorf(ix), fy0 = floorf(iy);
                int x0 = (int)fx0, y0 = (int)fy0;
                float wx1 = ix - fx0, wy1 = iy - fy0;
                float wx0 = 1.0f - wx1, wy0 = 1.0f - wy1;
                int x1 = min(x0 + 1, W - 1);
                int y1 = min(y0 + 1, H - 1);
                float w00 = wx0 * wy0, w01 = wx1 * wy0;
                float w10 = wx0 * wy1, w11 = wx1 * wy1;
                size_t base = (size_t)v * H * W;
                const float4* b00 = reinterpret_cast<const float4*>(&g_ft[(base + (size_t)y0*W + x0) * C]);
                const float4* b01 = reinterpret_cast<const float4*>(&g_ft[(base + (size_t)y0*W + x1) * C]);
                const float4* b10 = reinterpret_cast<const float4*>(&g_ft[(base + (size_t)y1*W + x0) * C]);
                const float4* b11 = reinterpret_cast<const float4*>(&g_ft[(base + (size_t)y1*W + x1) * C]);
#pragma unroll
                for (int q = 0; q < 4; q++) {
                    float4 p00 = __ldg(b00 + q);
                    float4 p01 = __ldg(b01 + q);
                    float4 p10 = __ldg(b10 + q);
                    float4 p11 = __ldg(b11 + q);
                    float v0 = w00*p00.x + w01*p01.x + w10*p10.x + w11*p11.x;
                    float v1 = w00*p00.y + w01*p01.y + w10*p10.y + w11*p11.y;
                    float v2 = w00*p00.z + w01*p01.z + w10*p10.z + w11*p11.z;
                    float v3 = w00*p00.w + w01*p01.w + w10*p10.w + w11*p11.w;
                    int c = q * 4;
                    sum[c+0] += v0; sq[c+0] += v0*v0;
                    sum[c+1] += v1; sq[c+1] += v1*v1;
                    sum[c+2] += v2; sq[c+2] += v2*v2;
                    sum[c+3] += v3; sq[c+3] += v3*v3;
                }
            }
        }
    }

    float denom = (msum <= 0.0f) ? 1e-8f : msum;
    float rd = 1.0f / denom;
#pragma unroll
    for (int c = 0; c < C; c++) {
        float mean = sum[c] * rd;
        float var  = sq[c] * rd - mean * mean;
        out[(size_t)c * P + p]       = mean;
        out[(size_t)(C + c) * P + p] = var;
    }
    out[(size_t)(2 * C) * P + p] = (msum > 1.0f) ? 1.0f : 0.0f;
}

// ---------------------------------------------------------------------------
extern "C" void kernel_launch(void* const* d_in, const int* in_sizes, int n_in,
                              void* d_out, int out_size) {
    const float* features = (const float*)d_in[0];  // (6,16,480,640)
    const float* intrs    = (const float*)d_in[1];  // (6,3,4)
    const float* c2ws     = (const float*)d_in[2];  // (6,4,4)
    float* out = (float*)d_out;                     // 33 * 96^3 floats

    prep_kernel<<<1, 32>>>(intrs, c2ws);
    transpose_kernel<<<NPIX / 256, 256>>>(features);
    vol_kernel<<<P / 256, 256>>>(out);
    (void)in_sizes; (void)n_in; (void)out_size;
}